// round 14
// baseline (speedup 1.0000x reference)
#include <cuda_runtime.h>
#include <cuda_fp16.h>
#include <cstdint>
#include <math.h>

// Problem constants
#define SQ   2048
#define H    4096
#define NQ   32
#define NKV  8
#define HD   128
#define II   14336
#define QKVN (NQ*HD + 2*NKV*HD)   // 6144
#define GUN  (2*II)               // 28672

// ---------------------------------------------------------------------------
// Scratch (device globals; no allocation anywhere)
// ---------------------------------------------------------------------------
__device__ __half g_xn   [SQ * H];
__device__ __half g_qkvh [SQ * QKVN];
__device__ __half g_attn [SQ * H];
__device__ __half g_xn2  [SQ * H];
__device__ __half g_hh   [(size_t)SQ * II];
__device__ float  g_res  [SQ * H];
__device__ __half g_wqkvT [(size_t)QKVN * H];
__device__ __half g_woT   [(size_t)H * H];
__device__ __half g_wguT  [(size_t)GUN * H];
__device__ __half g_wdownT[(size_t)H * II];

// ---------------------------------------------------------------------------
// Helpers
// ---------------------------------------------------------------------------
__device__ __forceinline__ void cp16(void* dst_smem, const void* src) {
    uint32_t d = (uint32_t)__cvta_generic_to_shared(dst_smem);
    asm volatile("cp.async.cg.shared.global [%0], [%1], 16;" :: "r"(d), "l"(src));
}
__device__ __forceinline__ void cp_commit() {
    asm volatile("cp.async.commit_group;" ::: "memory");
}
template <int N>
__device__ __forceinline__ void cp_wait() {
    asm volatile("cp.async.wait_group %0;" :: "n"(N) : "memory");
}
__device__ __forceinline__ void mma16816(float& c0, float& c1, float& c2, float& c3,
                                         uint32_t a0, uint32_t a1, uint32_t a2, uint32_t a3,
                                         uint32_t b0, uint32_t b1) {
    asm volatile(
        "mma.sync.aligned.m16n8k16.row.col.f32.f16.f16.f32 "
        "{%0,%1,%2,%3},{%4,%5,%6,%7},{%8,%9},{%0,%1,%2,%3};"
        : "+f"(c0), "+f"(c1), "+f"(c2), "+f"(c3)
        : "r"(a0), "r"(a1), "r"(a2), "r"(a3), "r"(b0), "r"(b1));
}
__device__ __forceinline__ void store_block_h2(half2* dst, const float* x) {
#pragma unroll
    for (int g = 0; g < 8; g++) {
        int pg = (g < 4) ? 2 * g : 2 * g - 7;
        dst[pg] = __floats2half2_rn(x[2 * g], x[2 * g + 1]);
    }
}

#define ROWB 160

// ---------------------------------------------------------------------------
// fp16 mma GEMM: 128x128x64 tiles, 256 threads, 2-stage cp.async, 2 CTA/SM.
// MODE: 0 = f32 out, 1 = f32 out + f32 residual, 2 = half K-permuted out.
// Grid: x = M blocks (fastest).
// ---------------------------------------------------------------------------
#define GSTG (256 * ROWB)          // 40960 B per stage
#define GEMM_SMEM (2 * GSTG)       // 81920 B

template <int MODE>
__global__ void __launch_bounds__(256, 2)
gemm_f16_kernel(int M, int N, int K,
                const __half* __restrict__ A,
                const __half* __restrict__ Bt,
                void* __restrict__ Cout,
                const float* __restrict__ R) {
    extern __shared__ char sm[];

    const int tid  = threadIdx.x;
    const int wid  = tid >> 5;
    const int lane = tid & 31;
    const int wm   = wid >> 2;       // 0..1
    const int wn   = wid & 3;        // 0..3
    const int q    = lane & 3;
    const int g8   = lane >> 2;
    const int m0   = blockIdx.x * 128;   // M fastest
    const int n0   = blockIdx.y * 128;
    const int KT   = K >> 6;

    auto load_stage = [&](int slot, int kt) {
        char* aS = sm + slot * GSTG;
        char* bS = aS + 128 * ROWB;
        const __half* Ag = A  + (size_t)m0 * K + (size_t)kt * 64;
        const __half* Bg = Bt + (size_t)n0 * K + (size_t)kt * 64;
#pragma unroll
        for (int j = 0; j < 4; j++) {
            int idx = tid + j * 256;
            int r = idx >> 3, c = idx & 7;
            cp16(aS + r * ROWB + c * 16, Ag + (size_t)r * K + c * 8);
            cp16(bS + r * ROWB + c * 16, Bg + (size_t)r * K + c * 8);
        }
    };

    load_stage(0, 0);
    cp_commit();

    float acc[4][4][4];
#pragma unroll
    for (int mt = 0; mt < 4; mt++)
#pragma unroll
        for (int nt = 0; nt < 4; nt++)
#pragma unroll
            for (int c = 0; c < 4; c++) acc[mt][nt][c] = 0.f;

    for (int kt = 0; kt < KT; kt++) {
        if (kt + 1 < KT) load_stage((kt + 1) & 1, kt + 1);
        cp_commit();
        cp_wait<1>();
        __syncthreads();

        char* aS = sm + (kt & 1) * GSTG;
        char* bS = aS + 128 * ROWB;

#pragma unroll
        for (int ks = 0; ks < 4; ks++) {
            int fo = ks * 32 + q * 8;
            uint2 bf[4];
#pragma unroll
            for (int nt = 0; nt < 4; nt++)
                bf[nt] = *(const uint2*)(bS + (wn * 32 + nt * 8 + g8) * ROWB + fo);
#pragma unroll
            for (int mt = 0; mt < 4; mt++) {
                int row = wm * 64 + mt * 16 + g8;
                uint2 aL = *(const uint2*)(aS + row * ROWB + fo);
                uint2 aH = *(const uint2*)(aS + (row + 8) * ROWB + fo);
#pragma unroll
                for (int nt = 0; nt < 4; nt++)
                    mma16816(acc[mt][nt][0], acc[mt][nt][1], acc[mt][nt][2], acc[mt][nt][3],
                             aL.x, aH.x, aL.y, aH.y, bf[nt].x, bf[nt].y);
            }
        }
        __syncthreads();
    }

    if (MODE == 2) {
        half2* Ch = (half2*)Cout;
        const int slotq = 2 * q;
#pragma unroll
        for (int mt = 0; mt < 4; mt++) {
            size_t r0 = (size_t)(m0 + wm * 64 + mt * 16 + g8);
            size_t r1 = r0 + 8;
#pragma unroll
            for (int nt = 0; nt < 4; nt++) {
                int gb = n0 + wn * 32 + nt * 8;
                size_t blk2 = (size_t)((gb & ~15) >> 1);
                int slot = slotq + (nt & 1);
                Ch[r0 * (N / 2) + blk2 + slot] = __floats2half2_rn(acc[mt][nt][0], acc[mt][nt][1]);
                Ch[r1 * (N / 2) + blk2 + slot] = __floats2half2_rn(acc[mt][nt][2], acc[mt][nt][3]);
            }
        }
    } else {
        float* C = (float*)Cout;
#pragma unroll
        for (int mt = 0; mt < 4; mt++) {
            int r0 = m0 + wm * 64 + mt * 16 + g8;
#pragma unroll
            for (int nt = 0; nt < 4; nt++) {
                int cc = n0 + wn * 32 + nt * 8 + 2 * q;
                float2 v0 = make_float2(acc[mt][nt][0], acc[mt][nt][1]);
                float2 v1 = make_float2(acc[mt][nt][2], acc[mt][nt][3]);
                if (MODE == 1) {
                    float2 r = *(const float2*)&R[(size_t)r0 * N + cc];
                    v0.x += r.x; v0.y += r.y;
                    r = *(const float2*)&R[(size_t)(r0 + 8) * N + cc];
                    v1.x += r.x; v1.y += r.y;
                }
                *(float2*)&C[(size_t)r0 * N + cc]       = v0;
                *(float2*)&C[(size_t)(r0 + 8) * N + cc] = v1;
            }
        }
    }
}

// ---------------------------------------------------------------------------
// Fused gate/up GEMM + SiLU (128x128, 256 threads, 3-stage, 1 CTA/SM).
// ---------------------------------------------------------------------------
#define GUST (128 * ROWB)
#define FSTAGE_BYTES (3 * GUST)
#define FGU_SMEM (3 * FSTAGE_BYTES)

__global__ void __launch_bounds__(256, 1)
gemm_gateup_silu_kernel(int M, int K,
                        const __half* __restrict__ A,
                        const __half* __restrict__ Bt,   // [GUN][K]
                        __half* __restrict__ HHout) {
    extern __shared__ char sm[];

    const int tid  = threadIdx.x;
    const int wid  = tid >> 5;
    const int lane = tid & 31;
    const int wm   = wid >> 2;
    const int wn   = wid & 3;
    const int q    = lane & 3;
    const int g8   = lane >> 2;
    const int m0   = blockIdx.x * 128;
    const int n0   = blockIdx.y * 128;
    const int KT   = K >> 6;

    const __half* BG = Bt + (size_t)n0 * K;
    const __half* BU = Bt + (size_t)(II + n0) * K;

    auto load_stage = [&](int slot, int kt) {
        char* aS = sm + slot * FSTAGE_BYTES;
        char* gS = aS + GUST;
        char* uS = gS + GUST;
        const __half* Ag = A + (size_t)m0 * K + (size_t)kt * 64;
        const __half* Gg = BG + (size_t)kt * 64;
        const __half* Ug = BU + (size_t)kt * 64;
#pragma unroll
        for (int j = 0; j < 4; j++) {
            int idx = tid + j * 256;
            int r = idx >> 3;
            int c = idx & 7;
            cp16(aS + r * ROWB + c * 16, Ag + (size_t)r * K + c * 8);
            cp16(gS + r * ROWB + c * 16, Gg + (size_t)r * K + c * 8);
            cp16(uS + r * ROWB + c * 16, Ug + (size_t)r * K + c * 8);
        }
    };

#pragma unroll
    for (int s = 0; s < 2; s++) {
        load_stage(s, s);
        cp_commit();
    }

    float accG[4][4][4], accU[4][4][4];
#pragma unroll
    for (int mt = 0; mt < 4; mt++)
#pragma unroll
        for (int nt = 0; nt < 4; nt++)
#pragma unroll
            for (int c = 0; c < 4; c++) { accG[mt][nt][c] = 0.f; accU[mt][nt][c] = 0.f; }

    for (int kt = 0; kt < KT; kt++) {
        cp_wait<1>();
        __syncthreads();

        int nk = kt + 2;
        if (nk < KT) load_stage(nk % 3, nk);
        cp_commit();

        char* aS = sm + (kt % 3) * FSTAGE_BYTES;
        char* gS = aS + GUST;
        char* uS = gS + GUST;

#pragma unroll
        for (int ks = 0; ks < 4; ks++) {
            int fo = ks * 32 + q * 8;
            uint2 bg[4], bu[4];
#pragma unroll
            for (int nt = 0; nt < 4; nt++) {
                int roff = (wn * 32 + nt * 8 + g8) * ROWB + fo;
                bg[nt] = *(const uint2*)(gS + roff);
                bu[nt] = *(const uint2*)(uS + roff);
            }
#pragma unroll
            for (int mt = 0; mt < 4; mt++) {
                int row = wm * 64 + mt * 16 + g8;
                uint2 aL = *(const uint2*)(aS + row * ROWB + fo);
                uint2 aH = *(const uint2*)(aS + (row + 8) * ROWB + fo);
#pragma unroll
                for (int nt = 0; nt < 4; nt++) {
                    mma16816(accG[mt][nt][0], accG[mt][nt][1], accG[mt][nt][2], accG[mt][nt][3],
                             aL.x, aH.x, aL.y, aH.y, bg[nt].x, bg[nt].y);
                    mma16816(accU[mt][nt][0], accU[mt][nt][1], accU[mt][nt][2], accU[mt][nt][3],
                             aL.x, aH.x, aL.y, aH.y, bu[nt].x, bu[nt].y);
                }
            }
        }
    }

    const int slotq = 2 * q;
#pragma unroll
    for (int mt = 0; mt < 4; mt++) {
        size_t r0 = (size_t)(m0 + wm * 64 + mt * 16 + g8);
        size_t r1 = r0 + 8;
#pragma unroll
        for (int nt = 0; nt < 4; nt++) {
            int gb = n0 + wn * 32 + nt * 8;
            size_t blk2 = (size_t)((gb & ~15) >> 1);
            int slot = slotq + (nt & 1);
            float g0 = accG[mt][nt][0], g1 = accG[mt][nt][1];
            float g2 = accG[mt][nt][2], g3 = accG[mt][nt][3];
            float u0 = accU[mt][nt][0], u1 = accU[mt][nt][1];
            float u2 = accU[mt][nt][2], u3 = accU[mt][nt][3];
            float s0 = g0 / (1.f + __expf(-g0)) * u0;
            float s1 = g1 / (1.f + __expf(-g1)) * u1;
            float s2 = g2 / (1.f + __expf(-g2)) * u2;
            float s3 = g3 / (1.f + __expf(-g3)) * u3;
            ((half2*)HHout)[r0 * (II / 2) + blk2 + slot] = __floats2half2_rn(s0, s1);
            ((half2*)HHout)[r1 * (II / 2) + blk2 + slot] = __floats2half2_rn(s2, s3);
        }
    }
}

// ---------------------------------------------------------------------------
// Weight transpose v2: 64(k) x 64(n) tiles, float4 reads, half2 writes.
// ---------------------------------------------------------------------------
__global__ void transpose_kernel(const float* __restrict__ in, __half* __restrict__ out,
                                 int Kd, int Nd) {
    __shared__ float tile[64][68];
    int k0 = blockIdx.y * 64, n0 = blockIdx.x * 64;
    int t = threadIdx.x;           // 256

    int rr = t >> 4;               // 0..15
    int c4 = (t & 15) * 4;
#pragma unroll
    for (int j = 0; j < 4; j++) {
        int r = rr + j * 16;
        float4 v = *(const float4*)&in[(size_t)(k0 + r) * Nd + n0 + c4];
        tile[r][c4 + 0] = v.x;
        tile[r][c4 + 1] = v.y;
        tile[r][c4 + 2] = v.z;
        tile[r][c4 + 3] = v.w;
    }
    __syncthreads();

    int n = t >> 2;                // 0..63
    half2* orow = (half2*)(out + (size_t)(n0 + n) * Kd + k0);
#pragma unroll
    for (int j = 0; j < 8; j++) {
        int g2 = (t & 3) + 4 * j;  // 0..31
        int b = g2 >> 3, g = g2 & 7;
        int pg = (g < 4) ? 2 * g : 2 * g - 7;
        orow[b * 8 + pg] = __floats2half2_rn(tile[2 * g2][n], tile[2 * g2 + 1][n]);
    }
}

// ---------------------------------------------------------------------------
// RMSNorm -> half, K-permuted
// ---------------------------------------------------------------------------
__global__ void rmsnorm_perm_kernel(const float* __restrict__ x,
                                    const float* __restrict__ w,
                                    __half* __restrict__ y) {
    int row = blockIdx.x;
    const float4* xr = (const float4*)(x + (size_t)row * H);

    float s = 0.f;
    for (int i = threadIdx.x; i < H / 4; i += 256) {
        float4 v = xr[i];
        s += v.x * v.x + v.y * v.y + v.z * v.z + v.w * v.w;
    }
    __shared__ float red[256];
    red[threadIdx.x] = s;
    __syncthreads();
    for (int off = 128; off; off >>= 1) {
        if (threadIdx.x < off) red[threadIdx.x] += red[threadIdx.x + off];
        __syncthreads();
    }
    float inv = rsqrtf(red[0] / (float)H + 1e-5f);

    int b = threadIdx.x;
    float xv[16];
    const float* xp = x + (size_t)row * H + b * 16;
    const float* wp = w + b * 16;
#pragma unroll
    for (int j = 0; j < 16; j++) xv[j] = xp[j] * inv * wp[j];
    store_block_h2((half2*)(y + (size_t)row * H + b * 16), xv);
}

// ---------------------------------------------------------------------------
// RoPE in place on half K-permuted qkv. 256 threads cover 4 heads per block.
// ---------------------------------------------------------------------------
__device__ __forceinline__ int stored_d(int d) {
    int b = d >> 4, x = d & 15, g = x >> 1, odd = x & 1;
    int pg = (g < 4) ? 2 * g : 2 * g - 7;
    return b * 16 + 2 * pg + odd;
}

__global__ void rope_h_kernel(const int* __restrict__ pos, __half* __restrict__ qkv) {
    int s  = blockIdx.x;
    int hh = blockIdx.y * 4 + (threadIdx.x >> 6);   // 0..39
    int i  = threadIdx.x & 63;
    int base = (hh < NQ) ? hh * HD : NQ * HD + (hh - NQ) * HD;
    __half* p = qkv + (size_t)s * QKVN + base;

    int s1 = stored_d(i), s2 = stored_d(i + 64);
    float fpos = (float)pos[s];
    float invf = powf(10000.0f, -(float)i / 64.0f);
    float ang  = fpos * invf;
    float sn, cs;
    sincosf(ang, &sn, &cs);
    float x1 = __half2float(p[s1]), x2 = __half2float(p[s2]);
    p[s1] = __float2half_rn(x1 * cs - x2 * sn);
    p[s2] = __float2half_rn(x2 * cs + x1 * sn);
}

// ---------------------------------------------------------------------------
// fp16 tensor-core flash attention (causal, GQA G=4).
// ---------------------------------------------------------------------------
#define FQROW 144
#define FVROW 80
#define OFFH_KS (128 * FQROW)
#define OFFH_VT (OFFH_KS + 64 * FQROW)
#define OFFH_PS (OFFH_VT + 128 * FVROW)
#define FA2_SMEM ((OFFH_PS + 128 * FVROW) * 2)

__global__ void __launch_bounds__(256, 1)
flash2_kernel(const __half* __restrict__ qkv, __half* __restrict__ attn) {
    extern __shared__ __half sh[];
    __half* Qs = sh;
    __half* Ks = sh + OFFH_KS;
    __half* Vt = sh + OFFH_VT;
    __half* Ps = sh + OFFH_PS;

    const int qb   = blockIdx.x;
    const int h    = blockIdx.y;
    const int kh   = h >> 2;
    const int tid  = threadIdx.x;
    const int wq   = tid >> 5;
    const int lane = tid & 31;
    const int g8   = lane >> 2;
    const int q    = lane & 3;
    const float scale = 0.08838834764831845f;

    {
        const __half* Qg = qkv + (size_t)(qb * 128) * QKVN + h * HD;
#pragma unroll
        for (int j = 0; j < 8; j++) {
            int idx = tid + j * 256;
            int r = idx >> 4, c = idx & 15;
            cp16((char*)Qs + r * (FQROW * 2) + c * 16, Qg + (size_t)r * QKVN + c * 8);
        }
        cp_commit();
    }

    float o[16][4];
#pragma unroll
    for (int nt = 0; nt < 16; nt++)
#pragma unroll
        for (int c = 0; c < 4; c++) o[nt][c] = 0.f;
    float m0 = -1e30f, m1 = -1e30f, l0 = 0.f, l1 = 0.f;

    const int row0g = qb * 128 + wq * 16 + g8;
    const int row1g = row0g + 8;
    const int jmax  = 2 * qb + 1;

    for (int jt = 0; jt <= jmax; jt++) {
        __syncthreads();
        {
            const __half* Kg = qkv + (size_t)(jt * 64) * QKVN + NQ * HD + kh * HD;
#pragma unroll
            for (int j = 0; j < 4; j++) {
                int idx = tid + j * 256;
                int r = idx >> 4, c = idx & 15;
                cp16((char*)Ks + r * (FQROW * 2) + c * 16, Kg + (size_t)r * QKVN + c * 8);
            }
            cp_commit();
        }
        {
            const __half* Vg = qkv + (size_t)(jt * 64) * QKVN + (NQ + NKV) * HD + kh * HD;
            for (int i = tid; i < 64 * 64; i += 256) {
                int r  = i >> 6;
                int gd = i & 63;
                half2 v = *(const half2*)(Vg + (size_t)r * QKVN + gd * 2);
                int blk = r >> 4, w = r & 15, g = w >> 1, odd = w & 1;
                int pg = (g < 4) ? 2 * g : 2 * g - 7;
                int pr = blk * 16 + pg * 2 + odd;
                Vt[(2 * gd + 0) * FVROW + pr] = __low2half(v);
                Vt[(2 * gd + 1) * FVROW + pr] = __high2half(v);
            }
        }
        cp_wait<0>();
        __syncthreads();

        float sacc[8][4];
#pragma unroll
        for (int nt = 0; nt < 8; nt++)
#pragma unroll
            for (int c = 0; c < 4; c++) sacc[nt][c] = 0.f;

#pragma unroll
        for (int ks = 0; ks < 8; ks++) {
            int fo = ks * 32 + q * 8;
            uint2 aL = *(const uint2*)((const char*)&Qs[(wq * 16 + g8) * FQROW] + fo);
            uint2 aH = *(const uint2*)((const char*)&Qs[(wq * 16 + g8 + 8) * FQROW] + fo);
#pragma unroll
            for (int nt = 0; nt < 8; nt++) {
                uint2 b = *(const uint2*)((const char*)&Ks[(nt * 8 + g8) * FQROW] + fo);
                mma16816(sacc[nt][0], sacc[nt][1], sacc[nt][2], sacc[nt][3],
                         aL.x, aH.x, aL.y, aH.y, b.x, b.y);
            }
        }
#pragma unroll
        for (int nt = 0; nt < 8; nt++)
#pragma unroll
            for (int c = 0; c < 4; c++) sacc[nt][c] *= scale;

        if (jt >= 2 * qb) {
#pragma unroll
            for (int nt = 0; nt < 8; nt++) {
                int kc = jt * 64 + nt * 8 + 2 * q;
                if (kc > row0g)     sacc[nt][0] = -1e30f;
                if (kc + 1 > row0g) sacc[nt][1] = -1e30f;
                if (kc > row1g)     sacc[nt][2] = -1e30f;
                if (kc + 1 > row1g) sacc[nt][3] = -1e30f;
            }
        }

        float rmax0 = -1e30f, rmax1 = -1e30f;
#pragma unroll
        for (int nt = 0; nt < 8; nt++) {
            rmax0 = fmaxf(rmax0, fmaxf(sacc[nt][0], sacc[nt][1]));
            rmax1 = fmaxf(rmax1, fmaxf(sacc[nt][2], sacc[nt][3]));
        }
        rmax0 = fmaxf(rmax0, __shfl_xor_sync(0xffffffffu, rmax0, 1));
        rmax0 = fmaxf(rmax0, __shfl_xor_sync(0xffffffffu, rmax0, 2));
        rmax1 = fmaxf(rmax1, __shfl_xor_sync(0xffffffffu, rmax1, 1));
        rmax1 = fmaxf(rmax1, __shfl_xor_sync(0xffffffffu, rmax1, 2));

        float nm0 = fmaxf(m0, rmax0), nm1 = fmaxf(m1, rmax1);
        float al0 = __expf(m0 - nm0), al1 = __expf(m1 - nm1);
        m0 = nm0; m1 = nm1;

        float sum0 = 0.f, sum1 = 0.f;
        half2* ps0 = (half2*)&Ps[(wq * 16 + g8) * FVROW];
        half2* ps1 = (half2*)&Ps[(wq * 16 + g8 + 8) * FVROW];
#pragma unroll
        for (int nt = 0; nt < 8; nt++) {
            float p00 = __expf(sacc[nt][0] - nm0);
            float p01 = __expf(sacc[nt][1] - nm0);
            float p10 = __expf(sacc[nt][2] - nm1);
            float p11 = __expf(sacc[nt][3] - nm1);
            sum0 += p00 + p01;
            sum1 += p10 + p11;
            int slot = (nt >> 1) * 8 + 2 * q + (nt & 1);
            ps0[slot] = __floats2half2_rn(p00, p01);
            ps1[slot] = __floats2half2_rn(p10, p11);
        }
        sum0 += __shfl_xor_sync(0xffffffffu, sum0, 1);
        sum0 += __shfl_xor_sync(0xffffffffu, sum0, 2);
        sum1 += __shfl_xor_sync(0xffffffffu, sum1, 1);
        sum1 += __shfl_xor_sync(0xffffffffu, sum1, 2);
        l0 = l0 * al0 + sum0;
        l1 = l1 * al1 + sum1;

#pragma unroll
        for (int nt = 0; nt < 16; nt++) {
            o[nt][0] *= al0; o[nt][1] *= al0;
            o[nt][2] *= al1; o[nt][3] *= al1;
        }

        __syncwarp();
#pragma unroll
        for (int ks = 0; ks < 4; ks++) {
            int fo = ks * 32 + q * 8;
            uint2 aL = *(const uint2*)((const char*)&Ps[(wq * 16 + g8) * FVROW] + fo);
            uint2 aH = *(const uint2*)((const char*)&Ps[(wq * 16 + g8 + 8) * FVROW] + fo);
#pragma unroll
            for (int nt = 0; nt < 16; nt++) {
                uint2 b = *(const uint2*)((const char*)&Vt[(nt * 8 + g8) * FVROW] + fo);
                mma16816(o[nt][0], o[nt][1], o[nt][2], o[nt][3],
                         aL.x, aH.x, aL.y, aH.y, b.x, b.y);
            }
        }
    }

    float invl0 = 1.f / l0, invl1 = 1.f / l1;
    half2* a0p = (half2*)(attn + (size_t)row0g * H + h * HD);
    half2* a1p = (half2*)(attn + (size_t)row1g * H + h * HD);
#pragma unroll
    for (int nt = 0; nt < 16; nt++) {
        a0p[nt * 4 + q] = __floats2half2_rn(o[nt][0] * invl0, o[nt][1] * invl0);
        a1p[nt * 4 + q] = __floats2half2_rn(o[nt][2] * invl1, o[nt][3] * invl1);
    }
}

// ---------------------------------------------------------------------------
// Launch
// ---------------------------------------------------------------------------
template <typename P, typename T>
static P sym_addr(T& symbol) {
    void* p = nullptr;
    cudaGetSymbolAddress(&p, symbol);
    return (P)p;
}

extern "C" void kernel_launch(void* const* d_in, const int* in_sizes, int n_in,
                              void* d_out, int out_size) {
    const int*   positions = (const int*)d_in[0];
    const float* hidden    = (const float*)d_in[1];
    const float* w_qkv     = (const float*)d_in[2];
    const float* w_o       = (const float*)d_in[3];
    const float* w_gu      = (const float*)d_in[4];
    const float* w_down    = (const float*)d_in[5];
    const float* ln1       = (const float*)d_in[6];
    const float* ln2       = (const float*)d_in[7];
    float*       out       = (float*)d_out;

    __half* xn     = sym_addr<__half*>(g_xn);
    __half* qkvh   = sym_addr<__half*>(g_qkvh);
    __half* attn   = sym_addr<__half*>(g_attn);
    __half* xn2    = sym_addr<__half*>(g_xn2);
    __half* hh     = sym_addr<__half*>(g_hh);
    __half* wqkvT  = sym_addr<__half*>(g_wqkvT);
    __half* woT    = sym_addr<__half*>(g_woT);
    __half* wguT   = sym_addr<__half*>(g_wguT);
    __half* wdownT = sym_addr<__half*>(g_wdownT);

    float* resid = (out_size >= 2 * SQ * H) ? out + (size_t)SQ * H : sym_addr<float*>(g_res);

    cudaFuncSetAttribute(flash2_kernel, cudaFuncAttributeMaxDynamicSharedMemorySize, FA2_SMEM);
    cudaFuncSetAttribute(gemm_f16_kernel<0>, cudaFuncAttributeMaxDynamicSharedMemorySize, GEMM_SMEM);
    cudaFuncSetAttribute(gemm_f16_kernel<1>, cudaFuncAttributeMaxDynamicSharedMemorySize, GEMM_SMEM);
    cudaFuncSetAttribute(gemm_f16_kernel<2>, cudaFuncAttributeMaxDynamicSharedMemorySize, GEMM_SMEM);
    cudaFuncSetAttribute(gemm_gateup_silu_kernel, cudaFuncAttributeMaxDynamicSharedMemorySize, FGU_SMEM);

    // 0. weight transposes (half + K-permuted), 64x64 tiles
    transpose_kernel<<<dim3(QKVN / 64, H / 64),  256>>>(w_qkv,  wqkvT,  H,  QKVN);
    transpose_kernel<<<dim3(H / 64,    H / 64),  256>>>(w_o,    woT,    H,  H);
    transpose_kernel<<<dim3(GUN / 64,  H / 64),  256>>>(w_gu,   wguT,   H,  GUN);
    transpose_kernel<<<dim3(H / 64,   II / 64),  256>>>(w_down, wdownT, II, H);

    // 1. rmsnorm1 (half perm)
    rmsnorm_perm_kernel<<<SQ, 256>>>(hidden, ln1, xn);
    // 2. qkv = xn @ w_qkv -> half perm
    gemm_f16_kernel<2><<<dim3(SQ / 128, QKVN / 128), 256, GEMM_SMEM>>>(SQ, QKVN, H, xn, wqkvT, qkvh, nullptr);
    // 3. rope (fp16 in place, batched)
    rope_h_kernel<<<dim3(SQ, (NQ + NKV) / 4), 256>>>(positions, qkvh);
    // 4. fp16 flash attention
    flash2_kernel<<<dim3(SQ / 128, NQ), 256, FA2_SMEM>>>(qkvh, attn);
    // 5. residual = attn @ w_o + hidden (fp32 out)
    gemm_f16_kernel<1><<<dim3(SQ / 128, H / 128), 256, GEMM_SMEM>>>(SQ, H, H, attn, woT, resid, hidden);
    // 6. rmsnorm2 (half perm)
    rmsnorm_perm_kernel<<<SQ, 256>>>(resid, ln2, xn2);
    // 7+8. hh = silu(xn2 @ wg) * (xn2 @ wu)
    gemm_gateup_silu_kernel<<<dim3(SQ / 128, II / 128), 256, FGU_SMEM>>>(SQ, H, xn2, wguT, hh);
    // 9. out = hh @ w_down (fp32 out)
    gemm_f16_kernel<0><<<dim3(SQ / 128, H / 128), 256, GEMM_SMEM>>>(SQ, H, II, hh, wdownT, out, nullptr);
}

// round 15
// speedup vs baseline: 1.0050x; 1.0050x over previous
#include <cuda_runtime.h>
#include <cuda_fp16.h>
#include <cstdint>
#include <math.h>

// Problem constants
#define SQ   2048
#define H    4096
#define NQ   32
#define NKV  8
#define HD   128
#define II   14336
#define QKVN (NQ*HD + 2*NKV*HD)   // 6144
#define GUN  (2*II)               // 28672

// ---------------------------------------------------------------------------
// Scratch (device globals; no allocation anywhere)
// ---------------------------------------------------------------------------
__device__ __half g_xn   [SQ * H];
__device__ __half g_qkvh [SQ * QKVN];
__device__ __half g_attn [SQ * H];
__device__ __half g_xn2  [SQ * H];
__device__ __half g_hh   [(size_t)SQ * II];
__device__ float  g_res  [SQ * H];
__device__ __half g_wqkvT [(size_t)QKVN * H];
__device__ __half g_woT   [(size_t)H * H];
__device__ __half g_wguT  [(size_t)GUN * H];
__device__ __half g_wdownT[(size_t)H * II];

// ---------------------------------------------------------------------------
// Helpers
// ---------------------------------------------------------------------------
__device__ __forceinline__ void cp16(void* dst_smem, const void* src) {
    uint32_t d = (uint32_t)__cvta_generic_to_shared(dst_smem);
    asm volatile("cp.async.cg.shared.global [%0], [%1], 16;" :: "r"(d), "l"(src));
}
__device__ __forceinline__ void cp_commit() {
    asm volatile("cp.async.commit_group;" ::: "memory");
}
template <int N>
__device__ __forceinline__ void cp_wait() {
    asm volatile("cp.async.wait_group %0;" :: "n"(N) : "memory");
}
__device__ __forceinline__ void mma16816(float& c0, float& c1, float& c2, float& c3,
                                         uint32_t a0, uint32_t a1, uint32_t a2, uint32_t a3,
                                         uint32_t b0, uint32_t b1) {
    asm volatile(
        "mma.sync.aligned.m16n8k16.row.col.f32.f16.f16.f32 "
        "{%0,%1,%2,%3},{%4,%5,%6,%7},{%8,%9},{%0,%1,%2,%3};"
        : "+f"(c0), "+f"(c1), "+f"(c2), "+f"(c3)
        : "r"(a0), "r"(a1), "r"(a2), "r"(a3), "r"(b0), "r"(b1));
}
__device__ __forceinline__ void store_block_h2(half2* dst, const float* x) {
#pragma unroll
    for (int g = 0; g < 8; g++) {
        int pg = (g < 4) ? 2 * g : 2 * g - 7;
        dst[pg] = __floats2half2_rn(x[2 * g], x[2 * g + 1]);
    }
}

#define ROWB 160

// ---------------------------------------------------------------------------
// fp16 mma GEMM: 128x128x64 tiles, 256 threads, 2-stage cp.async, 2 CTA/SM.
// MODE: 0 = f32 out, 1 = f32 out + f32 residual, 2 = half K-permuted out.
// Grid: x = M blocks (fastest).
// ---------------------------------------------------------------------------
#define GSTG (256 * ROWB)          // 40960 B per stage
#define GEMM_SMEM (2 * GSTG)       // 81920 B

template <int MODE>
__global__ void __launch_bounds__(256, 2)
gemm_f16_kernel(int M, int N, int K,
                const __half* __restrict__ A,
                const __half* __restrict__ Bt,
                void* __restrict__ Cout,
                const float* __restrict__ R) {
    extern __shared__ char sm[];

    const int tid  = threadIdx.x;
    const int wid  = tid >> 5;
    const int lane = tid & 31;
    const int wm   = wid >> 2;       // 0..1
    const int wn   = wid & 3;        // 0..3
    const int q    = lane & 3;
    const int g8   = lane >> 2;
    const int m0   = blockIdx.x * 128;   // M fastest
    const int n0   = blockIdx.y * 128;
    const int KT   = K >> 6;

    auto load_stage = [&](int slot, int kt) {
        char* aS = sm + slot * GSTG;
        char* bS = aS + 128 * ROWB;
        const __half* Ag = A  + (size_t)m0 * K + (size_t)kt * 64;
        const __half* Bg = Bt + (size_t)n0 * K + (size_t)kt * 64;
#pragma unroll
        for (int j = 0; j < 4; j++) {
            int idx = tid + j * 256;
            int r = idx >> 3, c = idx & 7;
            cp16(aS + r * ROWB + c * 16, Ag + (size_t)r * K + c * 8);
            cp16(bS + r * ROWB + c * 16, Bg + (size_t)r * K + c * 8);
        }
    };

    load_stage(0, 0);
    cp_commit();

    float acc[4][4][4];
#pragma unroll
    for (int mt = 0; mt < 4; mt++)
#pragma unroll
        for (int nt = 0; nt < 4; nt++)
#pragma unroll
            for (int c = 0; c < 4; c++) acc[mt][nt][c] = 0.f;

    for (int kt = 0; kt < KT; kt++) {
        if (kt + 1 < KT) load_stage((kt + 1) & 1, kt + 1);
        cp_commit();
        cp_wait<1>();
        __syncthreads();

        char* aS = sm + (kt & 1) * GSTG;
        char* bS = aS + 128 * ROWB;

#pragma unroll
        for (int ks = 0; ks < 4; ks++) {
            int fo = ks * 32 + q * 8;
            uint2 bf[4];
#pragma unroll
            for (int nt = 0; nt < 4; nt++)
                bf[nt] = *(const uint2*)(bS + (wn * 32 + nt * 8 + g8) * ROWB + fo);
#pragma unroll
            for (int mt = 0; mt < 4; mt++) {
                int row = wm * 64 + mt * 16 + g8;
                uint2 aL = *(const uint2*)(aS + row * ROWB + fo);
                uint2 aH = *(const uint2*)(aS + (row + 8) * ROWB + fo);
#pragma unroll
                for (int nt = 0; nt < 4; nt++)
                    mma16816(acc[mt][nt][0], acc[mt][nt][1], acc[mt][nt][2], acc[mt][nt][3],
                             aL.x, aH.x, aL.y, aH.y, bf[nt].x, bf[nt].y);
            }
        }
        __syncthreads();
    }

    if (MODE == 2) {
        half2* Ch = (half2*)Cout;
        const int slotq = 2 * q;
#pragma unroll
        for (int mt = 0; mt < 4; mt++) {
            size_t r0 = (size_t)(m0 + wm * 64 + mt * 16 + g8);
            size_t r1 = r0 + 8;
#pragma unroll
            for (int nt = 0; nt < 4; nt++) {
                int gb = n0 + wn * 32 + nt * 8;
                size_t blk2 = (size_t)((gb & ~15) >> 1);
                int slot = slotq + (nt & 1);
                Ch[r0 * (N / 2) + blk2 + slot] = __floats2half2_rn(acc[mt][nt][0], acc[mt][nt][1]);
                Ch[r1 * (N / 2) + blk2 + slot] = __floats2half2_rn(acc[mt][nt][2], acc[mt][nt][3]);
            }
        }
    } else {
        float* C = (float*)Cout;
#pragma unroll
        for (int mt = 0; mt < 4; mt++) {
            int r0 = m0 + wm * 64 + mt * 16 + g8;
#pragma unroll
            for (int nt = 0; nt < 4; nt++) {
                int cc = n0 + wn * 32 + nt * 8 + 2 * q;
                float2 v0 = make_float2(acc[mt][nt][0], acc[mt][nt][1]);
                float2 v1 = make_float2(acc[mt][nt][2], acc[mt][nt][3]);
                if (MODE == 1) {
                    float2 r = *(const float2*)&R[(size_t)r0 * N + cc];
                    v0.x += r.x; v0.y += r.y;
                    r = *(const float2*)&R[(size_t)(r0 + 8) * N + cc];
                    v1.x += r.x; v1.y += r.y;
                }
                *(float2*)&C[(size_t)r0 * N + cc]       = v0;
                *(float2*)&C[(size_t)(r0 + 8) * N + cc] = v1;
            }
        }
    }
}

// ---------------------------------------------------------------------------
// Fused gate/up GEMM + SiLU (128x128, 256 threads, 3-stage, 1 CTA/SM).
// ---------------------------------------------------------------------------
#define GUST (128 * ROWB)
#define FSTAGE_BYTES (3 * GUST)
#define FGU_SMEM (3 * FSTAGE_BYTES)

__global__ void __launch_bounds__(256, 1)
gemm_gateup_silu_kernel(int M, int K,
                        const __half* __restrict__ A,
                        const __half* __restrict__ Bt,   // [GUN][K]
                        __half* __restrict__ HHout) {
    extern __shared__ char sm[];

    const int tid  = threadIdx.x;
    const int wid  = tid >> 5;
    const int lane = tid & 31;
    const int wm   = wid >> 2;
    const int wn   = wid & 3;
    const int q    = lane & 3;
    const int g8   = lane >> 2;
    const int m0   = blockIdx.x * 128;
    const int n0   = blockIdx.y * 128;
    const int KT   = K >> 6;

    const __half* BG = Bt + (size_t)n0 * K;
    const __half* BU = Bt + (size_t)(II + n0) * K;

    auto load_stage = [&](int slot, int kt) {
        char* aS = sm + slot * FSTAGE_BYTES;
        char* gS = aS + GUST;
        char* uS = gS + GUST;
        const __half* Ag = A + (size_t)m0 * K + (size_t)kt * 64;
        const __half* Gg = BG + (size_t)kt * 64;
        const __half* Ug = BU + (size_t)kt * 64;
#pragma unroll
        for (int j = 0; j < 4; j++) {
            int idx = tid + j * 256;
            int r = idx >> 3;
            int c = idx & 7;
            cp16(aS + r * ROWB + c * 16, Ag + (size_t)r * K + c * 8);
            cp16(gS + r * ROWB + c * 16, Gg + (size_t)r * K + c * 8);
            cp16(uS + r * ROWB + c * 16, Ug + (size_t)r * K + c * 8);
        }
    };

#pragma unroll
    for (int s = 0; s < 2; s++) {
        load_stage(s, s);
        cp_commit();
    }

    float accG[4][4][4], accU[4][4][4];
#pragma unroll
    for (int mt = 0; mt < 4; mt++)
#pragma unroll
        for (int nt = 0; nt < 4; nt++)
#pragma unroll
            for (int c = 0; c < 4; c++) { accG[mt][nt][c] = 0.f; accU[mt][nt][c] = 0.f; }

    for (int kt = 0; kt < KT; kt++) {
        cp_wait<1>();
        __syncthreads();

        int nk = kt + 2;
        if (nk < KT) load_stage(nk % 3, nk);
        cp_commit();

        char* aS = sm + (kt % 3) * FSTAGE_BYTES;
        char* gS = aS + GUST;
        char* uS = gS + GUST;

#pragma unroll
        for (int ks = 0; ks < 4; ks++) {
            int fo = ks * 32 + q * 8;
            uint2 bg[4], bu[4];
#pragma unroll
            for (int nt = 0; nt < 4; nt++) {
                int roff = (wn * 32 + nt * 8 + g8) * ROWB + fo;
                bg[nt] = *(const uint2*)(gS + roff);
                bu[nt] = *(const uint2*)(uS + roff);
            }
#pragma unroll
            for (int mt = 0; mt < 4; mt++) {
                int row = wm * 64 + mt * 16 + g8;
                uint2 aL = *(const uint2*)(aS + row * ROWB + fo);
                uint2 aH = *(const uint2*)(aS + (row + 8) * ROWB + fo);
#pragma unroll
                for (int nt = 0; nt < 4; nt++) {
                    mma16816(accG[mt][nt][0], accG[mt][nt][1], accG[mt][nt][2], accG[mt][nt][3],
                             aL.x, aH.x, aL.y, aH.y, bg[nt].x, bg[nt].y);
                    mma16816(accU[mt][nt][0], accU[mt][nt][1], accU[mt][nt][2], accU[mt][nt][3],
                             aL.x, aH.x, aL.y, aH.y, bu[nt].x, bu[nt].y);
                }
            }
        }
    }

    const int slotq = 2 * q;
#pragma unroll
    for (int mt = 0; mt < 4; mt++) {
        size_t r0 = (size_t)(m0 + wm * 64 + mt * 16 + g8);
        size_t r1 = r0 + 8;
#pragma unroll
        for (int nt = 0; nt < 4; nt++) {
            int gb = n0 + wn * 32 + nt * 8;
            size_t blk2 = (size_t)((gb & ~15) >> 1);
            int slot = slotq + (nt & 1);
            float g0 = accG[mt][nt][0], g1 = accG[mt][nt][1];
            float g2 = accG[mt][nt][2], g3 = accG[mt][nt][3];
            float u0 = accU[mt][nt][0], u1 = accU[mt][nt][1];
            float u2 = accU[mt][nt][2], u3 = accU[mt][nt][3];
            float s0 = g0 / (1.f + __expf(-g0)) * u0;
            float s1 = g1 / (1.f + __expf(-g1)) * u1;
            float s2 = g2 / (1.f + __expf(-g2)) * u2;
            float s3 = g3 / (1.f + __expf(-g3)) * u3;
            ((half2*)HHout)[r0 * (II / 2) + blk2 + slot] = __floats2half2_rn(s0, s1);
            ((half2*)HHout)[r1 * (II / 2) + blk2 + slot] = __floats2half2_rn(s2, s3);
        }
    }
}

// ---------------------------------------------------------------------------
// Weight transpose v2: 64(k) x 64(n) tiles, float4 reads, half2 writes.
// ---------------------------------------------------------------------------
__global__ void transpose_kernel(const float* __restrict__ in, __half* __restrict__ out,
                                 int Kd, int Nd) {
    __shared__ float tile[64][68];
    int k0 = blockIdx.y * 64, n0 = blockIdx.x * 64;
    int t = threadIdx.x;           // 256

    int rr = t >> 4;               // 0..15
    int c4 = (t & 15) * 4;
#pragma unroll
    for (int j = 0; j < 4; j++) {
        int r = rr + j * 16;
        float4 v = *(const float4*)&in[(size_t)(k0 + r) * Nd + n0 + c4];
        tile[r][c4 + 0] = v.x;
        tile[r][c4 + 1] = v.y;
        tile[r][c4 + 2] = v.z;
        tile[r][c4 + 3] = v.w;
    }
    __syncthreads();

    int n = t >> 2;                // 0..63
    half2* orow = (half2*)(out + (size_t)(n0 + n) * Kd + k0);
#pragma unroll
    for (int j = 0; j < 8; j++) {
        int g2 = (t & 3) + 4 * j;  // 0..31
        int b = g2 >> 3, g = g2 & 7;
        int pg = (g < 4) ? 2 * g : 2 * g - 7;
        orow[b * 8 + pg] = __floats2half2_rn(tile[2 * g2][n], tile[2 * g2 + 1][n]);
    }
}

// ---------------------------------------------------------------------------
// RMSNorm -> half, K-permuted
// ---------------------------------------------------------------------------
__global__ void rmsnorm_perm_kernel(const float* __restrict__ x,
                                    const float* __restrict__ w,
                                    __half* __restrict__ y) {
    int row = blockIdx.x;
    const float4* xr = (const float4*)(x + (size_t)row * H);

    float s = 0.f;
    for (int i = threadIdx.x; i < H / 4; i += 256) {
        float4 v = xr[i];
        s += v.x * v.x + v.y * v.y + v.z * v.z + v.w * v.w;
    }
    __shared__ float red[256];
    red[threadIdx.x] = s;
    __syncthreads();
    for (int off = 128; off; off >>= 1) {
        if (threadIdx.x < off) red[threadIdx.x] += red[threadIdx.x + off];
        __syncthreads();
    }
    float inv = rsqrtf(red[0] / (float)H + 1e-5f);

    int b = threadIdx.x;
    float xv[16];
    const float* xp = x + (size_t)row * H + b * 16;
    const float* wp = w + b * 16;
#pragma unroll
    for (int j = 0; j < 16; j++) xv[j] = xp[j] * inv * wp[j];
    store_block_h2((half2*)(y + (size_t)row * H + b * 16), xv);
}

// ---------------------------------------------------------------------------
// RoPE in place on half K-permuted qkv. 256 threads cover 4 heads per block.
// ---------------------------------------------------------------------------
__device__ __forceinline__ int stored_d(int d) {
    int b = d >> 4, x = d & 15, g = x >> 1, odd = x & 1;
    int pg = (g < 4) ? 2 * g : 2 * g - 7;
    return b * 16 + 2 * pg + odd;
}

__global__ void rope_h_kernel(const int* __restrict__ pos, __half* __restrict__ qkv) {
    int s  = blockIdx.x;
    int hh = blockIdx.y * 4 + (threadIdx.x >> 6);   // 0..39
    int i  = threadIdx.x & 63;
    int base = (hh < NQ) ? hh * HD : NQ * HD + (hh - NQ) * HD;
    __half* p = qkv + (size_t)s * QKVN + base;

    int s1 = stored_d(i), s2 = stored_d(i + 64);
    float fpos = (float)pos[s];
    float invf = powf(10000.0f, -(float)i / 64.0f);
    float ang  = fpos * invf;
    float sn, cs;
    sincosf(ang, &sn, &cs);
    float x1 = __half2float(p[s1]), x2 = __half2float(p[s2]);
    p[s1] = __float2half_rn(x1 * cs - x2 * sn);
    p[s2] = __float2half_rn(x2 * cs + x1 * sn);
}

// ---------------------------------------------------------------------------
// fp16 tensor-core flash attention (causal, GQA G=4).
// ---------------------------------------------------------------------------
#define FQROW 144
#define FVROW 80
#define OFFH_KS (128 * FQROW)
#define OFFH_VT (OFFH_KS + 64 * FQROW)
#define OFFH_PS (OFFH_VT + 128 * FVROW)
#define FA2_SMEM ((OFFH_PS + 128 * FVROW) * 2)

__global__ void __launch_bounds__(256, 1)
flash2_kernel(const __half* __restrict__ qkv, __half* __restrict__ attn) {
    extern __shared__ __half sh[];
    __half* Qs = sh;
    __half* Ks = sh + OFFH_KS;
    __half* Vt = sh + OFFH_VT;
    __half* Ps = sh + OFFH_PS;

    const int qb   = blockIdx.x;
    const int h    = blockIdx.y;
    const int kh   = h >> 2;
    const int tid  = threadIdx.x;
    const int wq   = tid >> 5;
    const int lane = tid & 31;
    const int g8   = lane >> 2;
    const int q    = lane & 3;
    const float scale = 0.08838834764831845f;

    {
        const __half* Qg = qkv + (size_t)(qb * 128) * QKVN + h * HD;
#pragma unroll
        for (int j = 0; j < 8; j++) {
            int idx = tid + j * 256;
            int r = idx >> 4, c = idx & 15;
            cp16((char*)Qs + r * (FQROW * 2) + c * 16, Qg + (size_t)r * QKVN + c * 8);
        }
        cp_commit();
    }

    float o[16][4];
#pragma unroll
    for (int nt = 0; nt < 16; nt++)
#pragma unroll
        for (int c = 0; c < 4; c++) o[nt][c] = 0.f;
    float m0 = -1e30f, m1 = -1e30f, l0 = 0.f, l1 = 0.f;

    const int row0g = qb * 128 + wq * 16 + g8;
    const int row1g = row0g + 8;
    const int jmax  = 2 * qb + 1;

    for (int jt = 0; jt <= jmax; jt++) {
        __syncthreads();
        {
            const __half* Kg = qkv + (size_t)(jt * 64) * QKVN + NQ * HD + kh * HD;
#pragma unroll
            for (int j = 0; j < 4; j++) {
                int idx = tid + j * 256;
                int r = idx >> 4, c = idx & 15;
                cp16((char*)Ks + r * (FQROW * 2) + c * 16, Kg + (size_t)r * QKVN + c * 8);
            }
            cp_commit();
        }
        {
            const __half* Vg = qkv + (size_t)(jt * 64) * QKVN + (NQ + NKV) * HD + kh * HD;
            for (int i = tid; i < 64 * 64; i += 256) {
                int r  = i >> 6;
                int gd = i & 63;
                half2 v = *(const half2*)(Vg + (size_t)r * QKVN + gd * 2);
                int blk = r >> 4, w = r & 15, g = w >> 1, odd = w & 1;
                int pg = (g < 4) ? 2 * g : 2 * g - 7;
                int pr = blk * 16 + pg * 2 + odd;
                Vt[(2 * gd + 0) * FVROW + pr] = __low2half(v);
                Vt[(2 * gd + 1) * FVROW + pr] = __high2half(v);
            }
        }
        cp_wait<0>();
        __syncthreads();

        float sacc[8][4];
#pragma unroll
        for (int nt = 0; nt < 8; nt++)
#pragma unroll
            for (int c = 0; c < 4; c++) sacc[nt][c] = 0.f;

#pragma unroll
        for (int ks = 0; ks < 8; ks++) {
            int fo = ks * 32 + q * 8;
            uint2 aL = *(const uint2*)((const char*)&Qs[(wq * 16 + g8) * FQROW] + fo);
            uint2 aH = *(const uint2*)((const char*)&Qs[(wq * 16 + g8 + 8) * FQROW] + fo);
#pragma unroll
            for (int nt = 0; nt < 8; nt++) {
                uint2 b = *(const uint2*)((const char*)&Ks[(nt * 8 + g8) * FQROW] + fo);
                mma16816(sacc[nt][0], sacc[nt][1], sacc[nt][2], sacc[nt][3],
                         aL.x, aH.x, aL.y, aH.y, b.x, b.y);
            }
        }
#pragma unroll
        for (int nt = 0; nt < 8; nt++)
#pragma unroll
            for (int c = 0; c < 4; c++) sacc[nt][c] *= scale;

        if (jt >= 2 * qb) {
#pragma unroll
            for (int nt = 0; nt < 8; nt++) {
                int kc = jt * 64 + nt * 8 + 2 * q;
                if (kc > row0g)     sacc[nt][0] = -1e30f;
                if (kc + 1 > row0g) sacc[nt][1] = -1e30f;
                if (kc > row1g)     sacc[nt][2] = -1e30f;
                if (kc + 1 > row1g) sacc[nt][3] = -1e30f;
            }
        }

        float rmax0 = -1e30f, rmax1 = -1e30f;
#pragma unroll
        for (int nt = 0; nt < 8; nt++) {
            rmax0 = fmaxf(rmax0, fmaxf(sacc[nt][0], sacc[nt][1]));
            rmax1 = fmaxf(rmax1, fmaxf(sacc[nt][2], sacc[nt][3]));
        }
        rmax0 = fmaxf(rmax0, __shfl_xor_sync(0xffffffffu, rmax0, 1));
        rmax0 = fmaxf(rmax0, __shfl_xor_sync(0xffffffffu, rmax0, 2));
        rmax1 = fmaxf(rmax1, __shfl_xor_sync(0xffffffffu, rmax1, 1));
        rmax1 = fmaxf(rmax1, __shfl_xor_sync(0xffffffffu, rmax1, 2));

        float nm0 = fmaxf(m0, rmax0), nm1 = fmaxf(m1, rmax1);
        float al0 = __expf(m0 - nm0), al1 = __expf(m1 - nm1);
        m0 = nm0; m1 = nm1;

        float sum0 = 0.f, sum1 = 0.f;
        half2* ps0 = (half2*)&Ps[(wq * 16 + g8) * FVROW];
        half2* ps1 = (half2*)&Ps[(wq * 16 + g8 + 8) * FVROW];
#pragma unroll
        for (int nt = 0; nt < 8; nt++) {
            float p00 = __expf(sacc[nt][0] - nm0);
            float p01 = __expf(sacc[nt][1] - nm0);
            float p10 = __expf(sacc[nt][2] - nm1);
            float p11 = __expf(sacc[nt][3] - nm1);
            sum0 += p00 + p01;
            sum1 += p10 + p11;
            int slot = (nt >> 1) * 8 + 2 * q + (nt & 1);
            ps0[slot] = __floats2half2_rn(p00, p01);
            ps1[slot] = __floats2half2_rn(p10, p11);
        }
        sum0 += __shfl_xor_sync(0xffffffffu, sum0, 1);
        sum0 += __shfl_xor_sync(0xffffffffu, sum0, 2);
        sum1 += __shfl_xor_sync(0xffffffffu, sum1, 1);
        sum1 += __shfl_xor_sync(0xffffffffu, sum1, 2);
        l0 = l0 * al0 + sum0;
        l1 = l1 * al1 + sum1;

#pragma unroll
        for (int nt = 0; nt < 16; nt++) {
            o[nt][0] *= al0; o[nt][1] *= al0;
            o[nt][2] *= al1; o[nt][3] *= al1;
        }

        __syncwarp();
#pragma unroll
        for (int ks = 0; ks < 4; ks++) {
            int fo = ks * 32 + q * 8;
            uint2 aL = *(const uint2*)((const char*)&Ps[(wq * 16 + g8) * FVROW] + fo);
            uint2 aH = *(const uint2*)((const char*)&Ps[(wq * 16 + g8 + 8) * FVROW] + fo);
#pragma unroll
            for (int nt = 0; nt < 16; nt++) {
                uint2 b = *(const uint2*)((const char*)&Vt[(nt * 8 + g8) * FVROW] + fo);
                mma16816(o[nt][0], o[nt][1], o[nt][2], o[nt][3],
                         aL.x, aH.x, aL.y, aH.y, b.x, b.y);
            }
        }
    }

    float invl0 = 1.f / l0, invl1 = 1.f / l1;
    half2* a0p = (half2*)(attn + (size_t)row0g * H + h * HD);
    half2* a1p = (half2*)(attn + (size_t)row1g * H + h * HD);
#pragma unroll
    for (int nt = 0; nt < 16; nt++) {
        a0p[nt * 4 + q] = __floats2half2_rn(o[nt][0] * invl0, o[nt][1] * invl0);
        a1p[nt * 4 + q] = __floats2half2_rn(o[nt][2] * invl1, o[nt][3] * invl1);
    }
}

// ---------------------------------------------------------------------------
// Launch: dual-stream. s2 carries the three late-weight transposes,
// overlapped with the qkv/rope/flash prefix; joined before the w_o GEMM.
// Stream/event create+destroy are host APIs (not graph nodes); the fork/join
// events become graph edges under capture.
// ---------------------------------------------------------------------------
template <typename P, typename T>
static P sym_addr(T& symbol) {
    void* p = nullptr;
    cudaGetSymbolAddress(&p, symbol);
    return (P)p;
}

extern "C" void kernel_launch(void* const* d_in, const int* in_sizes, int n_in,
                              void* d_out, int out_size) {
    const int*   positions = (const int*)d_in[0];
    const float* hidden    = (const float*)d_in[1];
    const float* w_qkv     = (const float*)d_in[2];
    const float* w_o       = (const float*)d_in[3];
    const float* w_gu      = (const float*)d_in[4];
    const float* w_down    = (const float*)d_in[5];
    const float* ln1       = (const float*)d_in[6];
    const float* ln2       = (const float*)d_in[7];
    float*       out       = (float*)d_out;

    __half* xn     = sym_addr<__half*>(g_xn);
    __half* qkvh   = sym_addr<__half*>(g_qkvh);
    __half* attn   = sym_addr<__half*>(g_attn);
    __half* xn2    = sym_addr<__half*>(g_xn2);
    __half* hh     = sym_addr<__half*>(g_hh);
    __half* wqkvT  = sym_addr<__half*>(g_wqkvT);
    __half* woT    = sym_addr<__half*>(g_woT);
    __half* wguT   = sym_addr<__half*>(g_wguT);
    __half* wdownT = sym_addr<__half*>(g_wdownT);

    float* resid = (out_size >= 2 * SQ * H) ? out + (size_t)SQ * H : sym_addr<float*>(g_res);

    cudaFuncSetAttribute(flash2_kernel, cudaFuncAttributeMaxDynamicSharedMemorySize, FA2_SMEM);
    cudaFuncSetAttribute(gemm_f16_kernel<0>, cudaFuncAttributeMaxDynamicSharedMemorySize, GEMM_SMEM);
    cudaFuncSetAttribute(gemm_f16_kernel<1>, cudaFuncAttributeMaxDynamicSharedMemorySize, GEMM_SMEM);
    cudaFuncSetAttribute(gemm_f16_kernel<2>, cudaFuncAttributeMaxDynamicSharedMemorySize, GEMM_SMEM);
    cudaFuncSetAttribute(gemm_gateup_silu_kernel, cudaFuncAttributeMaxDynamicSharedMemorySize, FGU_SMEM);

    // Fork a side stream for the three weight transposes that aren't needed
    // until the second half of the layer.
    cudaStream_t s2;
    cudaEvent_t evFork, evJoin;
    cudaStreamCreateWithFlags(&s2, cudaStreamNonBlocking);
    cudaEventCreateWithFlags(&evFork, cudaEventDisableTiming);
    cudaEventCreateWithFlags(&evJoin, cudaEventDisableTiming);

    cudaEventRecord(evFork, 0);
    cudaStreamWaitEvent(s2, evFork, 0);
    // s2: w_gu (largest first), w_down, w_o
    transpose_kernel<<<dim3(GUN / 64,  H / 64),  256, 0, s2>>>(w_gu,   wguT,   H,  GUN);
    transpose_kernel<<<dim3(H / 64,   II / 64),  256, 0, s2>>>(w_down, wdownT, II, H);
    transpose_kernel<<<dim3(H / 64,    H / 64),  256, 0, s2>>>(w_o,    woT,    H,  H);
    cudaEventRecord(evJoin, s2);

    // main stream: qkv path
    transpose_kernel<<<dim3(QKVN / 64, H / 64),  256>>>(w_qkv, wqkvT, H, QKVN);
    rmsnorm_perm_kernel<<<SQ, 256>>>(hidden, ln1, xn);
    gemm_f16_kernel<2><<<dim3(SQ / 128, QKVN / 128), 256, GEMM_SMEM>>>(SQ, QKVN, H, xn, wqkvT, qkvh, nullptr);
    rope_h_kernel<<<dim3(SQ, (NQ + NKV) / 4), 256>>>(positions, qkvh);
    flash2_kernel<<<dim3(SQ / 128, NQ), 256, FA2_SMEM>>>(qkvh, attn);

    // join: remaining GEMMs need the s2 transposes
    cudaStreamWaitEvent(0, evJoin, 0);

    gemm_f16_kernel<1><<<dim3(SQ / 128, H / 128), 256, GEMM_SMEM>>>(SQ, H, H, attn, woT, resid, hidden);
    rmsnorm_perm_kernel<<<SQ, 256>>>(resid, ln2, xn2);
    gemm_gateup_silu_kernel<<<dim3(SQ / 128, II / 128), 256, FGU_SMEM>>>(SQ, H, xn2, wguT, hh);
    gemm_f16_kernel<0><<<dim3(SQ / 128, H / 128), 256, GEMM_SMEM>>>(SQ, H, II, hh, wdownT, out, nullptr);

    cudaStreamDestroy(s2);
    cudaEventDestroy(evFork);
    cudaEventDestroy(evJoin);
}